// round 2
// baseline (speedup 1.0000x reference)
#include <cuda_runtime.h>
#include <math.h>

#define D_MODEL 1024
#define NHEAD 16
#define HEAD_DIM 64
#define MOE_HIDDEN 2048
#define NUM_EXPERTS 4
#define BATCH 8
#define SEQ 1024
#define TOKENS (BATCH*SEQ)          /* 8192  */
#define BND (TOKENS*D_MODEL)        /* 8388608 */
#define LN_EPS 1e-5f

// ---------------- scratch (device globals; no allocation) ----------------
__device__ float g_Tr[BND];                    // trend
__device__ float g_S[BND];                     // seasonal
__device__ float g_buf[BND];                   // Sn, then xf
__device__ float g_q[BND];
__device__ float g_k[BND];
__device__ float g_v[BND];
__device__ float g_y[BND];                     // attention output (pre O-proj)
__device__ float g_xs[BND];                    // x_s running residual
__device__ float g_h[TOKENS*MOE_HIDDEN];       // MoE hidden
__device__ float g_w[TOKENS*NUM_EXPERTS];      // routing weights (zeros for unselected)
__device__ float g_gates[TOKENS*NUM_EXPERTS];  // full softmax gates (for aux)

// ---------------- Decomp1D: 3 depthwise convs (reflect pad) + softmax mix ----------------
#define DC_NT 128
#define DC_DT 32
#define DC_HALO 24
__global__ void __launch_bounds__(256) decomp_kernel(
    const float* __restrict__ x, const float* __restrict__ alpha,
    const float* __restrict__ dw7, const float* __restrict__ dw25,
    const float* __restrict__ dw49)
{
    __shared__ float sx[DC_NT + 2*DC_HALO][DC_DT];
    __shared__ float sw7[DC_DT][7];
    __shared__ float sw25[DC_DT][25];
    __shared__ float sw49[DC_DT][49];
    const int b  = blockIdx.z;
    const int n0 = blockIdx.y * DC_NT;
    const int d0 = blockIdx.x * DC_DT;
    const int tid = threadIdx.x;

    for (int i = tid; i < DC_DT*7;  i += 256) sw7 [i/7 ][i%7 ] = dw7 [(d0 + i/7 )*7  + i%7 ];
    for (int i = tid; i < DC_DT*25; i += 256) sw25[i/25][i%25] = dw25[(d0 + i/25)*25 + i%25];
    for (int i = tid; i < DC_DT*49; i += 256) sw49[i/49][i%49] = dw49[(d0 + i/49)*49 + i%49];

    for (int i = tid; i < (DC_NT + 2*DC_HALO)*DC_DT; i += 256) {
        int r = i / DC_DT, c = i % DC_DT;
        int n = n0 + r - DC_HALO;
        if (n < 0)    n = -n;              // reflect (edge excluded)
        if (n >= SEQ) n = 2*SEQ - 2 - n;
        sx[r][c] = x[((size_t)b*SEQ + n)*D_MODEL + d0 + c];
    }
    __syncthreads();

    const float a0 = alpha[0], a1 = alpha[1], a2 = alpha[2];
    const float mx = fmaxf(a0, fmaxf(a1, a2));
    const float e0 = __expf(a0-mx), e1 = __expf(a1-mx), e2 = __expf(a2-mx);
    const float inv = 1.f/(e0+e1+e2);
    const float w0 = e0*inv, w1 = e1*inv, w2 = e2*inv;

    for (int i = tid; i < DC_NT*DC_DT; i += 256) {
        const int p = i / DC_DT, c = i % DC_DT;
        float t7 = 0.f, t25 = 0.f, t49 = 0.f;
        #pragma unroll
        for (int j = 0; j < 7;  j++) t7  = fmaf(sx[p + DC_HALO - 3  + j][c], sw7 [c][j], t7 );
        #pragma unroll
        for (int j = 0; j < 25; j++) t25 = fmaf(sx[p + DC_HALO - 12 + j][c], sw25[c][j], t25);
        #pragma unroll
        for (int j = 0; j < 49; j++) t49 = fmaf(sx[p + j][c],                sw49[c][j], t49);
        const float tr = w0*t7 + w1*t25 + w2*t49;
        const size_t idx = ((size_t)b*SEQ + n0 + p)*D_MODEL + d0 + c;
        g_Tr[idx] = tr;
        g_S[idx]  = sx[p + DC_HALO][c] - tr;
    }
}

// ---------------- LayerNorm (row per block) ----------------
__global__ void __launch_bounds__(256) ln_kernel(
    const float* __restrict__ in, const float* __restrict__ gam,
    const float* __restrict__ bet, float* __restrict__ out)
{
    __shared__ float row[D_MODEL];
    __shared__ float red[256];
    const int t = blockIdx.x, tid = threadIdx.x;
    const float* ip = in + (size_t)t*D_MODEL;
    float s = 0.f;
    for (int d = tid; d < D_MODEL; d += 256) { float v = ip[d]; row[d] = v; s += v; }
    red[tid] = s; __syncthreads();
    for (int o = 128; o > 0; o >>= 1) { if (tid < o) red[tid] += red[tid+o]; __syncthreads(); }
    const float mean = red[0] * (1.f/D_MODEL);
    __syncthreads();
    float vs = 0.f;
    for (int d = tid; d < D_MODEL; d += 256) { float dv = row[d]-mean; vs += dv*dv; }
    red[tid] = vs; __syncthreads();
    for (int o = 128; o > 0; o >>= 1) { if (tid < o) red[tid] += red[tid+o]; __syncthreads(); }
    const float rstd = rsqrtf(red[0] * (1.f/D_MODEL) + LN_EPS);
    for (int d = tid; d < D_MODEL; d += 256)
        out[(size_t)t*D_MODEL + d] = (row[d]-mean)*rstd*gam[d] + bet[d];
}

// ---------------- Tiled SGEMM:  C[m,n] = sum_k A[m,k]*B[n,k] (+bias, epilogue) ----------------
// EPI: 0 = plain, 1 = GELU(exact), 2 = +resid, 3 = moe accumulate (C += v*w[m,e])
template<int EPI>
__global__ void __launch_bounds__(256) gemm_kernel(
    const float* __restrict__ A, const float* __restrict__ B,
    const float* __restrict__ bias, float* __restrict__ C,
    int M, int Nn, int K,
    const float* __restrict__ resid, const float* __restrict__ wts, int expert)
{
    __shared__ float As[16][128];
    __shared__ float Bs[16][128];
    const int bm = blockIdx.y * 128, bn = blockIdx.x * 128;
    const int tid = threadIdx.x;
    const int tm = (tid / 16) * 8, tn = (tid % 16) * 8;
    const int lrow = tid >> 1, lcol = (tid & 1) * 4;
    const float* Ap = A + (size_t)(bm + lrow)*K + lcol;
    const float* Bp = B + (size_t)(bn + lrow)*K + lcol;

    float acc[8][8];
    #pragma unroll
    for (int i = 0; i < 8; i++)
        #pragma unroll
        for (int j = 0; j < 8; j++) acc[i][j] = 0.f;

    for (int k0 = 0; k0 < K; k0 += 16) {
        const float4 av0 = *(const float4*)(Ap + k0);
        const float4 av1 = *(const float4*)(Ap + k0 + 8);
        const float4 bv0 = *(const float4*)(Bp + k0);
        const float4 bv1 = *(const float4*)(Bp + k0 + 8);
        As[lcol+0][lrow] = av0.x; As[lcol+1][lrow] = av0.y;
        As[lcol+2][lrow] = av0.z; As[lcol+3][lrow] = av0.w;
        As[lcol+8][lrow] = av1.x; As[lcol+9][lrow] = av1.y;
        As[lcol+10][lrow] = av1.z; As[lcol+11][lrow] = av1.w;
        Bs[lcol+0][lrow] = bv0.x; Bs[lcol+1][lrow] = bv0.y;
        Bs[lcol+2][lrow] = bv0.z; Bs[lcol+3][lrow] = bv0.w;
        Bs[lcol+8][lrow] = bv1.x; Bs[lcol+9][lrow] = bv1.y;
        Bs[lcol+10][lrow] = bv1.z; Bs[lcol+11][lrow] = bv1.w;
        __syncthreads();
        #pragma unroll
        for (int kk = 0; kk < 16; kk++) {
            float a[8], b[8];
            #pragma unroll
            for (int i = 0; i < 8; i++) { a[i] = As[kk][tm+i]; b[i] = Bs[kk][tn+i]; }
            #pragma unroll
            for (int i = 0; i < 8; i++)
                #pragma unroll
                for (int j = 0; j < 8; j++) acc[i][j] = fmaf(a[i], b[j], acc[i][j]);
        }
        __syncthreads();
    }

    #pragma unroll
    for (int i = 0; i < 8; i++) {
        const int m = bm + tm + i;
        const float wmoe = (EPI == 3) ? wts[m*NUM_EXPERTS + expert] : 0.f;
        #pragma unroll
        for (int j = 0; j < 8; j++) {
            const int n = bn + tn + j;
            const float v = acc[i][j] + bias[n];
            const size_t idx = (size_t)m*Nn + n;
            if (EPI == 0)      C[idx] = v;
            else if (EPI == 1) C[idx] = 0.5f*v*(1.0f + erff(v*0.70710678118654752f));
            else if (EPI == 2) C[idx] = v + resid[idx];
            else               C[idx] += v*wmoe;
        }
    }
}

// ---------------- ALiBi attention (flash-style, fp32). Logits bounded -> no max-shift needed. ----------------
__global__ void __launch_bounds__(64) attn_kernel()
{
    __shared__ float Ks[64][64];
    __shared__ float Vs[64][64];
    const int bh = blockIdx.x;                  // 0..127
    const int b = bh / NHEAD, h = bh % NHEAD;
    const int q0 = blockIdx.y * 64;
    const int tid = threadIdx.x;                // q row within tile
    const int qg = q0 + tid;

    float q[64], o[64];
    const float* qp = g_q + ((size_t)(b*SEQ + qg))*D_MODEL + h*HEAD_DIM;
    #pragma unroll
    for (int d = 0; d < 64; d++) { q[d] = qp[d]*0.125f; o[d] = 0.f; }
    float l = 0.f;
    const float slope = exp2f(-0.5f*(float)(h+1));

    for (int k0 = 0; k0 < SEQ; k0 += 64) {
        const float* kp = g_k + ((size_t)(b*SEQ + k0))*D_MODEL + h*HEAD_DIM;
        const float* vp = g_v + ((size_t)(b*SEQ + k0))*D_MODEL + h*HEAD_DIM;
        __syncthreads();
        for (int r = 0; r < 64; r++) {
            Ks[r][tid] = kp[(size_t)r*D_MODEL + tid];
            Vs[r][tid] = vp[(size_t)r*D_MODEL + tid];
        }
        __syncthreads();
        #pragma unroll 4
        for (int j = 0; j < 64; j++) {
            float s = 0.f;
            #pragma unroll
            for (int d = 0; d < 64; d++) s = fmaf(q[d], Ks[j][d], s);
            const int dist = k0 + j - qg;
            if (dist > 0) s -= slope * (float)dist;
            const float p = __expf(s);
            l += p;
            #pragma unroll
            for (int d = 0; d < 64; d++) o[d] = fmaf(p, Vs[j][d], o[d]);
        }
    }
    const float invl = 1.f/l;
    float* yp = g_y + ((size_t)(b*SEQ + qg))*D_MODEL + h*HEAD_DIM;
    #pragma unroll
    for (int d = 0; d < 64; d++) yp[d] = o[d]*invl;
}

// ---------------- Router: softmax gates, top-2 (first-occurrence ties), normalized weights ----------------
__global__ void __launch_bounds__(256) router_kernel(
    const float* __restrict__ xf, const float* __restrict__ rw)
{
    const int warp = threadIdx.x / 32, lane = threadIdx.x % 32;
    const int t = blockIdx.x*8 + warp;
    const float* xp = xf + (size_t)t*D_MODEL;
    float logit[NUM_EXPERTS];
    #pragma unroll
    for (int e = 0; e < NUM_EXPERTS; e++) {
        float p = 0.f;
        for (int d = lane; d < D_MODEL; d += 32) p = fmaf(xp[d], rw[e*D_MODEL + d], p);
        #pragma unroll
        for (int o = 16; o > 0; o >>= 1) p += __shfl_xor_sync(0xffffffffu, p, o);
        logit[e] = p;
    }
    if (lane == 0) {
        float mx = logit[0];
        #pragma unroll
        for (int e = 1; e < NUM_EXPERTS; e++) mx = fmaxf(mx, logit[e]);
        float g[NUM_EXPERTS]; float s = 0.f;
        #pragma unroll
        for (int e = 0; e < NUM_EXPERTS; e++) { g[e] = expf(logit[e]-mx); s += g[e]; }
        #pragma unroll
        for (int e = 0; e < NUM_EXPERTS; e++) g[e] /= s;
        int i0 = 0;
        #pragma unroll
        for (int e = 1; e < NUM_EXPERTS; e++) if (g[e] > g[i0]) i0 = e;
        int i1 = -1;
        #pragma unroll
        for (int e = 0; e < NUM_EXPERTS; e++)
            if (e != i0 && (i1 < 0 || g[e] > g[i1])) i1 = e;
        const float s2 = fmaxf(g[i0] + g[i1], 1e-9f);
        float w[NUM_EXPERTS] = {0.f, 0.f, 0.f, 0.f};
        w[i0] = g[i0]/s2; w[i1] = g[i1]/s2;
        #pragma unroll
        for (int e = 0; e < NUM_EXPERTS; e++) {
            g_gates[t*NUM_EXPERTS + e] = g[e];
            g_w[t*NUM_EXPERTS + e]     = w[e];
        }
    }
}

// ---------------- aux (deterministic single-block reduction) ----------------
__global__ void __launch_bounds__(256) aux_kernel(float* __restrict__ out, int out_size)
{
    __shared__ float rg[NUM_EXPERTS][256];
    __shared__ float rc[NUM_EXPERTS][256];
    const int tid = threadIdx.x;
    float gs[NUM_EXPERTS] = {0,0,0,0}, cs[NUM_EXPERTS] = {0,0,0,0};
    for (int t = tid; t < TOKENS; t += 256) {
        #pragma unroll
        for (int e = 0; e < NUM_EXPERTS; e++) {
            gs[e] += g_gates[t*NUM_EXPERTS + e];
            cs[e] += (g_w[t*NUM_EXPERTS + e] > 0.f) ? 1.f : 0.f;
        }
    }
    #pragma unroll
    for (int e = 0; e < NUM_EXPERTS; e++) { rg[e][tid] = gs[e]; rc[e][tid] = cs[e]; }
    __syncthreads();
    for (int o = 128; o > 0; o >>= 1) {
        if (tid < o)
            #pragma unroll
            for (int e = 0; e < NUM_EXPERTS; e++) { rg[e][tid] += rg[e][tid+o]; rc[e][tid] += rc[e][tid+o]; }
        __syncthreads();
    }
    if (tid == 0 && out_size > BND) {
        float aux = 0.f;
        #pragma unroll
        for (int e = 0; e < NUM_EXPERTS; e++)
            aux += (rg[e][0]*(1.f/TOKENS)) * (rc[e][0]*(1.f/TOKENS));
        out[out_size - 1] = (float)NUM_EXPERTS * aux;
    }
}

// ---------------- final: out = x_s + depthwise conv5(Tr, zero pad) + tb ----------------
__global__ void __launch_bounds__(256) final_kernel(
    const float* __restrict__ tw, const float* __restrict__ tb, float* __restrict__ out)
{
    const size_t gid = (size_t)blockIdx.x*256 + threadIdx.x;
    if (gid >= (size_t)BND) return;
    const int d = (int)(gid % D_MODEL);
    const int n = (int)((gid / D_MODEL) % SEQ);
    float t = 0.f;
    #pragma unroll
    for (int j = 0; j < 5; j++) {
        const int nn = n - 2 + j;
        if (nn >= 0 && nn < SEQ)
            t = fmaf(g_Tr[gid + (size_t)(j-2)*D_MODEL], tw[d*5 + j], t);
    }
    out[gid] = g_xs[gid] + t + tb[d];
}

// ---------------- launch ----------------
static float* sym_addr(const void* sym) {
    void* p = nullptr;
    cudaGetSymbolAddress(&p, sym);
    return (float*)p;
}

extern "C" void kernel_launch(void* const* d_in, const int* in_sizes, int n_in,
                              void* d_out, int out_size)
{
    const float* x    = (const float*)d_in[0];
    const float* qw   = (const float*)d_in[1];  const float* qb  = (const float*)d_in[2];
    const float* kw   = (const float*)d_in[3];  const float* kb  = (const float*)d_in[4];
    const float* vw   = (const float*)d_in[5];  const float* vb  = (const float*)d_in[6];
    const float* ow   = (const float*)d_in[7];  const float* ob  = (const float*)d_in[8];
    const float* n1g  = (const float*)d_in[9];  const float* n1b = (const float*)d_in[10];
    const float* n2g  = (const float*)d_in[11]; const float* n2b = (const float*)d_in[12];
    const float* alpha= (const float*)d_in[13];
    const float* dw7  = (const float*)d_in[14];
    const float* dw25 = (const float*)d_in[15];
    const float* dw49 = (const float*)d_in[16];
    const float* rw   = (const float*)d_in[17];
    const float* ew1  = (const float*)d_in[18]; const float* eb1 = (const float*)d_in[19];
    const float* ew2  = (const float*)d_in[20]; const float* eb2 = (const float*)d_in[21];
    const float* tw   = (const float*)d_in[22]; const float* tb  = (const float*)d_in[23];
    float* out = (float*)d_out;

    float* pS   = sym_addr(g_S);
    float* pBuf = sym_addr(g_buf);
    float* pQ   = sym_addr(g_q);
    float* pK   = sym_addr(g_k);
    float* pV   = sym_addr(g_v);
    float* pY   = sym_addr(g_y);
    float* pXs  = sym_addr(g_xs);
    float* pH   = sym_addr(g_h);
    float* pW   = sym_addr(g_w);
    (void)in_sizes; (void)n_in;

    // 1) decomposition -> g_Tr, g_S
    dim3 dgrid(D_MODEL/DC_DT, SEQ/DC_NT, BATCH);
    decomp_kernel<<<dgrid, 256>>>(x, alpha, dw7, dw25, dw49);

    // 2) LN1(S) -> Sn (g_buf)
    ln_kernel<<<TOKENS, 256>>>(pS, n1g, n1b, pBuf);

    // 3) Q,K,V projections
    dim3 ggrid(D_MODEL/128, TOKENS/128);
    gemm_kernel<0><<<ggrid, 256>>>(pBuf, qw, qb, pQ, TOKENS, D_MODEL, D_MODEL, nullptr, nullptr, 0);
    gemm_kernel<0><<<ggrid, 256>>>(pBuf, kw, kb, pK, TOKENS, D_MODEL, D_MODEL, nullptr, nullptr, 0);
    gemm_kernel<0><<<ggrid, 256>>>(pBuf, vw, vb, pV, TOKENS, D_MODEL, D_MODEL, nullptr, nullptr, 0);

    // 4) attention -> g_y
    dim3 agrid(BATCH*NHEAD, SEQ/64);
    attn_kernel<<<agrid, 64>>>();

    // 5) O projection + residual S -> g_xs
    gemm_kernel<2><<<ggrid, 256>>>(pY, ow, ob, pXs, TOKENS, D_MODEL, D_MODEL, pS, nullptr, 0);

    // 6) LN2(x_s) -> xf (g_buf)
    ln_kernel<<<TOKENS, 256>>>(pXs, n2g, n2b, pBuf);

    // 7) router + aux
    router_kernel<<<TOKENS/8, 256>>>(pBuf, rw);
    aux_kernel<<<1, 256>>>(out, out_size);

    // 8) MoE FFN: dense over 4 experts, weighted accumulate into g_xs
    dim3 h1grid(MOE_HIDDEN/128, TOKENS/128);
    dim3 h2grid(D_MODEL/128,    TOKENS/128);
    for (int e = 0; e < NUM_EXPERTS; e++) {
        gemm_kernel<1><<<h1grid, 256>>>(pBuf, ew1 + (size_t)e*MOE_HIDDEN*D_MODEL,
                                        eb1 + (size_t)e*MOE_HIDDEN, pH,
                                        TOKENS, MOE_HIDDEN, D_MODEL, nullptr, nullptr, 0);
        gemm_kernel<3><<<h2grid, 256>>>(pH, ew2 + (size_t)e*D_MODEL*MOE_HIDDEN,
                                        eb2 + (size_t)e*D_MODEL, pXs,
                                        TOKENS, D_MODEL, MOE_HIDDEN, nullptr, pW, e);
    }

    // 9) final: trend conv + residual + aux already written
    final_kernel<<<(BND + 255)/256, 256>>>(tw, tb, out);
}

// round 4
// speedup vs baseline: 2.3252x; 2.3252x over previous
#include <cuda_runtime.h>
#include <math.h>
#include <stdint.h>

#define D_MODEL 1024
#define NHEAD 16
#define HEAD_DIM 64
#define MOE_HIDDEN 2048
#define NUM_EXPERTS 4
#define BATCH 8
#define SEQ 1024
#define TOKENS (BATCH*SEQ)          /* 8192  */
#define BND (TOKENS*D_MODEL)        /* 8388608 */
#define LN_EPS 1e-5f

// ---------------- scratch (device globals; no allocation) ----------------
__device__ float g_Tr[BND];
__device__ float g_S[BND];
__device__ float g_buf[BND];
__device__ float g_q[BND];
__device__ float g_k[BND];
__device__ float g_v[BND];
__device__ float g_y[BND];
__device__ float g_xs[BND];
__device__ float g_h[TOKENS*MOE_HIDDEN];
__device__ float g_w[TOKENS*NUM_EXPERTS];
__device__ float g_gates[TOKENS*NUM_EXPERTS];

// ============================================================
// tf32 helpers (sm_80+ PTX, no 'a'-suffix gating)
// ============================================================
__device__ __forceinline__ uint32_t f2tf32(float f) {
    uint32_t u; asm("cvt.rna.tf32.f32 %0, %1;" : "=r"(u) : "f"(f)); return u;
}
__device__ __forceinline__ void mma_tf32(float* c, const uint32_t* a, const uint32_t* b) {
    asm volatile(
        "mma.sync.aligned.m16n8k8.row.col.f32.tf32.tf32.f32 "
        "{%0,%1,%2,%3}, {%4,%5,%6,%7}, {%8,%9}, {%0,%1,%2,%3};"
        : "+f"(c[0]), "+f"(c[1]), "+f"(c[2]), "+f"(c[3])
        : "r"(a[0]), "r"(a[1]), "r"(a[2]), "r"(a[3]), "r"(b[0]), "r"(b[1]));
}

// ============================================================
// tf32 mma.sync GEMM: C[m,n] = sum_k A[m,k]*B[n,k] (+bias, epilogue)
// CTA tile 128x128, BK=32, 256 thr (8 warps 2x4, warp tile 64x32),
// double-buffered smem [128][36] (pad -> conflict-free frags),
// register-prefetch pipeline, ONE syncthreads per K-iter.
// EPI: 0 plain, 1 GELU, 2 +resid, 3 C += v*w[m,e]
// ============================================================
#define TCG_LDA 36
#define TCG_BUF (128*TCG_LDA)
#define TCG_SMEM (4*TCG_BUF*4)   /* 2 bufs x (A+B) = 73728 B */

template<int EPI>
__global__ void __launch_bounds__(256) tc_gemm(
    const float* __restrict__ A, const float* __restrict__ B,
    const float* __restrict__ bias, float* __restrict__ C,
    int K, int Nn,
    const float* __restrict__ resid, const float* __restrict__ wts, int expert)
{
    extern __shared__ uint32_t smu[];
    uint32_t* As = smu;                 // [2][128*36]
    uint32_t* Bs = smu + 2*TCG_BUF;
    const int tid  = threadIdx.x;
    const int warp = tid >> 5, lane = tid & 31;
    const int wm = (warp >> 2) * 64, wn = (warp & 3) * 32;
    const int g = lane >> 2, t = lane & 3;
    const int bm = blockIdx.y * 128, bn = blockIdx.x * 128;

    const int lr = tid >> 3, lc = tid & 7;   // staging row / col-of-float4
    const float* Ag = A + (size_t)(bm + lr) * K + lc * 4;
    const float* Bg = B + (size_t)(bn + lr) * K + lc * 4;

    float acc[4][4][4];
    #pragma unroll
    for (int i = 0; i < 4; i++)
        #pragma unroll
        for (int j = 0; j < 4; j++)
            #pragma unroll
            for (int r = 0; r < 4; r++) acc[i][j][r] = 0.f;

    const int NT = K >> 5;
    float4 pa[4], pb[4];
    #pragma unroll
    for (int p = 0; p < 4; p++) {
        pa[p] = *(const float4*)(Ag + (size_t)p*32*K);
        pb[p] = *(const float4*)(Bg + (size_t)p*32*K);
    }
    #pragma unroll
    for (int p = 0; p < 4; p++) {
        uint4 ua = { f2tf32(pa[p].x), f2tf32(pa[p].y), f2tf32(pa[p].z), f2tf32(pa[p].w) };
        uint4 ub = { f2tf32(pb[p].x), f2tf32(pb[p].y), f2tf32(pb[p].z), f2tf32(pb[p].w) };
        *(uint4*)&As[(lr + p*32)*TCG_LDA + lc*4] = ua;
        *(uint4*)&Bs[(lr + p*32)*TCG_LDA + lc*4] = ub;
    }
    __syncthreads();

    for (int kt = 0; kt < NT; kt++) {
        const int buf = kt & 1;
        const uint32_t* Ab = As + buf*TCG_BUF;
        const uint32_t* Bb = Bs + buf*TCG_BUF;
        if (kt + 1 < NT) {
            const int ko = (kt + 1) * 32;
            #pragma unroll
            for (int p = 0; p < 4; p++) {
                pa[p] = *(const float4*)(Ag + (size_t)p*32*K + ko);
                pb[p] = *(const float4*)(Bg + (size_t)p*32*K + ko);
            }
        }
        #pragma unroll
        for (int ks = 0; ks < 4; ks++) {
            const int kb = ks * 8;
            uint32_t af[4][4], bf[4][2];
            #pragma unroll
            for (int mf = 0; mf < 4; mf++) {
                const uint32_t* base = Ab + (wm + mf*16 + g)*TCG_LDA + kb + t;
                af[mf][0] = base[0];
                af[mf][1] = base[8*TCG_LDA];
                af[mf][2] = base[4];
                af[mf][3] = base[8*TCG_LDA + 4];
            }
            #pragma unroll
            for (int nf = 0; nf < 4; nf++) {
                const uint32_t* base = Bb + (wn + nf*8 + g)*TCG_LDA + kb + t;
                bf[nf][0] = base[0];
                bf[nf][1] = base[4];
            }
            #pragma unroll
            for (int mf = 0; mf < 4; mf++)
                #pragma unroll
                for (int nf = 0; nf < 4; nf++)
                    mma_tf32(acc[mf][nf], af[mf], bf[nf]);
        }
        if (kt + 1 < NT) {
            const int nb = (kt + 1) & 1;
            uint32_t* Ad = As + nb*TCG_BUF;
            uint32_t* Bd = Bs + nb*TCG_BUF;
            #pragma unroll
            for (int p = 0; p < 4; p++) {
                uint4 ua = { f2tf32(pa[p].x), f2tf32(pa[p].y), f2tf32(pa[p].z), f2tf32(pa[p].w) };
                uint4 ub = { f2tf32(pb[p].x), f2tf32(pb[p].y), f2tf32(pb[p].z), f2tf32(pb[p].w) };
                *(uint4*)&Ad[(lr + p*32)*TCG_LDA + lc*4] = ua;
                *(uint4*)&Bd[(lr + p*32)*TCG_LDA + lc*4] = ub;
            }
            __syncthreads();
        }
    }

    // ---- epilogue: fragments straight to global ----
    #pragma unroll
    for (int mf = 0; mf < 4; mf++) {
        const int m0 = bm + wm + mf*16 + g;
        const int m1 = m0 + 8;
        float w0 = 0.f, w1 = 0.f;
        if (EPI == 3) {
            w0 = wts[m0*NUM_EXPERTS + expert];
            w1 = wts[m1*NUM_EXPERTS + expert];
        }
        #pragma unroll
        for (int nf = 0; nf < 4; nf++) {
            const int n0 = bn + wn + nf*8 + 2*t;
            const float b0 = bias[n0], b1 = bias[n0 + 1];
            float v0 = acc[mf][nf][0] + b0;
            float v1 = acc[mf][nf][1] + b1;
            float v2 = acc[mf][nf][2] + b0;
            float v3 = acc[mf][nf][3] + b1;
            const size_t i0 = (size_t)m0 * Nn + n0;
            const size_t i1 = (size_t)m1 * Nn + n0;
            if (EPI == 0) {
                C[i0] = v0; C[i0+1] = v1; C[i1] = v2; C[i1+1] = v3;
            } else if (EPI == 1) {
                C[i0]   = 0.5f*v0*(1.0f + erff(v0*0.70710678118654752f));
                C[i0+1] = 0.5f*v1*(1.0f + erff(v1*0.70710678118654752f));
                C[i1]   = 0.5f*v2*(1.0f + erff(v2*0.70710678118654752f));
                C[i1+1] = 0.5f*v3*(1.0f + erff(v3*0.70710678118654752f));
            } else if (EPI == 2) {
                C[i0] = v0 + resid[i0]; C[i0+1] = v1 + resid[i0+1];
                C[i1] = v2 + resid[i1]; C[i1+1] = v3 + resid[i1+1];
            } else {
                C[i0] += v0*w0; C[i0+1] += v1*w0;
                C[i1] += v2*w1; C[i1+1] += v3*w1;
            }
        }
    }
}

// ---------------- Decomp1D ----------------
#define DC_NT 128
#define DC_DT 32
#define DC_HALO 24
__global__ void __launch_bounds__(256) decomp_kernel(
    const float* __restrict__ x, const float* __restrict__ alpha,
    const float* __restrict__ dw7, const float* __restrict__ dw25,
    const float* __restrict__ dw49)
{
    __shared__ float sx[DC_NT + 2*DC_HALO][DC_DT];
    __shared__ float sw7[DC_DT][7];
    __shared__ float sw25[DC_DT][25];
    __shared__ float sw49[DC_DT][49];
    const int b  = blockIdx.z;
    const int n0 = blockIdx.y * DC_NT;
    const int d0 = blockIdx.x * DC_DT;
    const int tid = threadIdx.x;

    for (int i = tid; i < DC_DT*7;  i += 256) sw7 [i/7 ][i%7 ] = dw7 [(d0 + i/7 )*7  + i%7 ];
    for (int i = tid; i < DC_DT*25; i += 256) sw25[i/25][i%25] = dw25[(d0 + i/25)*25 + i%25];
    for (int i = tid; i < DC_DT*49; i += 256) sw49[i/49][i%49] = dw49[(d0 + i/49)*49 + i%49];

    for (int i = tid; i < (DC_NT + 2*DC_HALO)*DC_DT; i += 256) {
        int r = i / DC_DT, c = i % DC_DT;
        int n = n0 + r - DC_HALO;
        if (n < 0)    n = -n;
        if (n >= SEQ) n = 2*SEQ - 2 - n;
        sx[r][c] = x[((size_t)b*SEQ + n)*D_MODEL + d0 + c];
    }
    __syncthreads();

    const float a0 = alpha[0], a1 = alpha[1], a2 = alpha[2];
    const float mx = fmaxf(a0, fmaxf(a1, a2));
    const float e0 = __expf(a0-mx), e1 = __expf(a1-mx), e2 = __expf(a2-mx);
    const float inv = 1.f/(e0+e1+e2);
    const float w0 = e0*inv, w1 = e1*inv, w2 = e2*inv;

    for (int i = tid; i < DC_NT*DC_DT; i += 256) {
        const int p = i / DC_DT, c = i % DC_DT;
        float t7 = 0.f, t25 = 0.f, t49 = 0.f;
        #pragma unroll
        for (int j = 0; j < 7;  j++) t7  = fmaf(sx[p + DC_HALO - 3  + j][c], sw7 [c][j], t7 );
        #pragma unroll
        for (int j = 0; j < 25; j++) t25 = fmaf(sx[p + DC_HALO - 12 + j][c], sw25[c][j], t25);
        #pragma unroll
        for (int j = 0; j < 49; j++) t49 = fmaf(sx[p + j][c],                sw49[c][j], t49);
        const float tr = w0*t7 + w1*t25 + w2*t49;
        const size_t idx = ((size_t)b*SEQ + n0 + p)*D_MODEL + d0 + c;
        g_Tr[idx] = tr;
        g_S[idx]  = sx[p + DC_HALO][c] - tr;
    }
}

// ---------------- LayerNorm ----------------
__global__ void __launch_bounds__(256) ln_kernel(
    const float* __restrict__ in, const float* __restrict__ gam,
    const float* __restrict__ bet, float* __restrict__ out)
{
    __shared__ float row[D_MODEL];
    __shared__ float red[256];
    const int t = blockIdx.x, tid = threadIdx.x;
    const float* ip = in + (size_t)t*D_MODEL;
    float s = 0.f;
    for (int d = tid; d < D_MODEL; d += 256) { float v = ip[d]; row[d] = v; s += v; }
    red[tid] = s; __syncthreads();
    for (int o = 128; o > 0; o >>= 1) { if (tid < o) red[tid] += red[tid+o]; __syncthreads(); }
    const float mean = red[0] * (1.f/D_MODEL);
    __syncthreads();
    float vs = 0.f;
    for (int d = tid; d < D_MODEL; d += 256) { float dv = row[d]-mean; vs += dv*dv; }
    red[tid] = vs; __syncthreads();
    for (int o = 128; o > 0; o >>= 1) { if (tid < o) red[tid] += red[tid+o]; __syncthreads(); }
    const float rstd = rsqrtf(red[0] * (1.f/D_MODEL) + LN_EPS);
    for (int d = tid; d < D_MODEL; d += 256)
        out[(size_t)t*D_MODEL + d] = (row[d]-mean)*rstd*gam[d] + bet[d];
}

// ---------------- ALiBi attention ----------------
__global__ void __launch_bounds__(64) attn_kernel()
{
    __shared__ float Ks[64][64];
    __shared__ float Vs[64][64];
    const int bh = blockIdx.x;
    const int b = bh / NHEAD, h = bh % NHEAD;
    const int q0 = blockIdx.y * 64;
    const int tid = threadIdx.x;
    const int qg = q0 + tid;

    float q[64], o[64];
    const float* qp = g_q + ((size_t)(b*SEQ + qg))*D_MODEL + h*HEAD_DIM;
    #pragma unroll
    for (int d = 0; d < 64; d++) { q[d] = qp[d]*0.125f; o[d] = 0.f; }
    float l = 0.f;
    const float slope = exp2f(-0.5f*(float)(h+1));

    for (int k0 = 0; k0 < SEQ; k0 += 64) {
        const float* kp = g_k + ((size_t)(b*SEQ + k0))*D_MODEL + h*HEAD_DIM;
        const float* vp = g_v + ((size_t)(b*SEQ + k0))*D_MODEL + h*HEAD_DIM;
        __syncthreads();
        for (int r = 0; r < 64; r++) {
            Ks[r][tid] = kp[(size_t)r*D_MODEL + tid];
            Vs[r][tid] = vp[(size_t)r*D_MODEL + tid];
        }
        __syncthreads();
        #pragma unroll 4
        for (int j = 0; j < 64; j++) {
            float s = 0.f;
            #pragma unroll
            for (int d = 0; d < 64; d++) s = fmaf(q[d], Ks[j][d], s);
            const int dist = k0 + j - qg;
            if (dist > 0) s -= slope * (float)dist;
            const float p = __expf(s);
            l += p;
            #pragma unroll
            for (int d = 0; d < 64; d++) o[d] = fmaf(p, Vs[j][d], o[d]);
        }
    }
    const float invl = 1.f/l;
    float* yp = g_y + ((size_t)(b*SEQ + qg))*D_MODEL + h*HEAD_DIM;
    #pragma unroll
    for (int d = 0; d < 64; d++) yp[d] = o[d]*invl;
}

// ---------------- Router ----------------
__global__ void __launch_bounds__(256) router_kernel(
    const float* __restrict__ xf, const float* __restrict__ rw)
{
    const int warp = threadIdx.x / 32, lane = threadIdx.x % 32;
    const int t = blockIdx.x*8 + warp;
    const float* xp = xf + (size_t)t*D_MODEL;
    float logit[NUM_EXPERTS];
    #pragma unroll
    for (int e = 0; e < NUM_EXPERTS; e++) {
        float p = 0.f;
        for (int d = lane; d < D_MODEL; d += 32) p = fmaf(xp[d], rw[e*D_MODEL + d], p);
        #pragma unroll
        for (int o = 16; o > 0; o >>= 1) p += __shfl_xor_sync(0xffffffffu, p, o);
        logit[e] = p;
    }
    if (lane == 0) {
        float mx = logit[0];
        #pragma unroll
        for (int e = 1; e < NUM_EXPERTS; e++) mx = fmaxf(mx, logit[e]);
        float g[NUM_EXPERTS]; float s = 0.f;
        #pragma unroll
        for (int e = 0; e < NUM_EXPERTS; e++) { g[e] = expf(logit[e]-mx); s += g[e]; }
        #pragma unroll
        for (int e = 0; e < NUM_EXPERTS; e++) g[e] /= s;
        int i0 = 0;
        #pragma unroll
        for (int e = 1; e < NUM_EXPERTS; e++) if (g[e] > g[i0]) i0 = e;
        int i1 = -1;
        #pragma unroll
        for (int e = 0; e < NUM_EXPERTS; e++)
            if (e != i0 && (i1 < 0 || g[e] > g[i1])) i1 = e;
        const float s2 = fmaxf(g[i0] + g[i1], 1e-9f);
        float w[NUM_EXPERTS] = {0.f, 0.f, 0.f, 0.f};
        w[i0] = g[i0]/s2; w[i1] = g[i1]/s2;
        #pragma unroll
        for (int e = 0; e < NUM_EXPERTS; e++) {
            g_gates[t*NUM_EXPERTS + e] = g[e];
            g_w[t*NUM_EXPERTS + e]     = w[e];
        }
    }
}

// ---------------- aux ----------------
__global__ void __launch_bounds__(256) aux_kernel(float* __restrict__ out, int out_size)
{
    __shared__ float rg[NUM_EXPERTS][256];
    __shared__ float rc[NUM_EXPERTS][256];
    const int tid = threadIdx.x;
    float gs[NUM_EXPERTS] = {0,0,0,0}, cs[NUM_EXPERTS] = {0,0,0,0};
    for (int t = tid; t < TOKENS; t += 256) {
        #pragma unroll
        for (int e = 0; e < NUM_EXPERTS; e++) {
            gs[e] += g_gates[t*NUM_EXPERTS + e];
            cs[e] += (g_w[t*NUM_EXPERTS + e] > 0.f) ? 1.f : 0.f;
        }
    }
    #pragma unroll
    for (int e = 0; e < NUM_EXPERTS; e++) { rg[e][tid] = gs[e]; rc[e][tid] = cs[e]; }
    __syncthreads();
    for (int o = 128; o > 0; o >>= 1) {
        if (tid < o)
            #pragma unroll
            for (int e = 0; e < NUM_EXPERTS; e++) { rg[e][tid] += rg[e][tid+o]; rc[e][tid] += rc[e][tid+o]; }
        __syncthreads();
    }
    if (tid == 0 && out_size > BND) {
        float aux = 0.f;
        #pragma unroll
        for (int e = 0; e < NUM_EXPERTS; e++)
            aux += (rg[e][0]*(1.f/TOKENS)) * (rc[e][0]*(1.f/TOKENS));
        out[out_size - 1] = (float)NUM_EXPERTS * aux;
    }
}

// ---------------- final ----------------
__global__ void __launch_bounds__(256) final_kernel(
    const float* __restrict__ tw, const float* __restrict__ tb, float* __restrict__ out)
{
    const size_t gid = (size_t)blockIdx.x*256 + threadIdx.x;
    if (gid >= (size_t)BND) return;
    const int d = (int)(gid % D_MODEL);
    const int n = (int)((gid / D_MODEL) % SEQ);
    float t = 0.f;
    #pragma unroll
    for (int j = 0; j < 5; j++) {
        const int nn = n - 2 + j;
        if (nn >= 0 && nn < SEQ)
            t = fmaf(g_Tr[gid + (size_t)(j-2)*D_MODEL], tw[d*5 + j], t);
    }
    out[gid] = g_xs[gid] + t + tb[d];
}

// ---------------- launch ----------------
static float* sym_addr(const void* sym) {
    void* p = nullptr;
    cudaGetSymbolAddress(&p, sym);
    return (float*)p;
}

extern "C" void kernel_launch(void* const* d_in, const int* in_sizes, int n_in,
                              void* d_out, int out_size)
{
    const float* x    = (const float*)d_in[0];
    const float* qw   = (const float*)d_in[1];  const float* qb  = (const float*)d_in[2];
    const float* kw   = (const float*)d_in[3];  const float* kb  = (const float*)d_in[4];
    const float* vw   = (const float*)d_in[5];  const float* vb  = (const float*)d_in[6];
    const float* ow   = (const float*)d_in[7];  const float* ob  = (const float*)d_in[8];
    const float* n1g  = (const float*)d_in[9];  const float* n1b = (const float*)d_in[10];
    const float* n2g  = (const float*)d_in[11]; const float* n2b = (const float*)d_in[12];
    const float* alpha= (const float*)d_in[13];
    const float* dw7  = (const float*)d_in[14];
    const float* dw25 = (const float*)d_in[15];
    const float* dw49 = (const float*)d_in[16];
    const float* rw   = (const float*)d_in[17];
    const float* ew1  = (const float*)d_in[18]; const float* eb1 = (const float*)d_in[19];
    const float* ew2  = (const float*)d_in[20]; const float* eb2 = (const float*)d_in[21];
    const float* tw   = (const float*)d_in[22]; const float* tb  = (const float*)d_in[23];
    float* out = (float*)d_out;

    float* pS   = sym_addr(g_S);
    float* pBuf = sym_addr(g_buf);
    float* pQ   = sym_addr(g_q);
    float* pK   = sym_addr(g_k);
    float* pV   = sym_addr(g_v);
    float* pY   = sym_addr(g_y);
    float* pXs  = sym_addr(g_xs);
    float* pH   = sym_addr(g_h);
    float* pW   = sym_addr(g_w);
    (void)in_sizes; (void)n_in;

    cudaFuncSetAttribute(tc_gemm<0>, cudaFuncAttributeMaxDynamicSharedMemorySize, TCG_SMEM);
    cudaFuncSetAttribute(tc_gemm<1>, cudaFuncAttributeMaxDynamicSharedMemorySize, TCG_SMEM);
    cudaFuncSetAttribute(tc_gemm<2>, cudaFuncAttributeMaxDynamicSharedMemorySize, TCG_SMEM);
    cudaFuncSetAttribute(tc_gemm<3>, cudaFuncAttributeMaxDynamicSharedMemorySize, TCG_SMEM);

    // 1) decomposition -> g_Tr, g_S
    dim3 dgrid(D_MODEL/DC_DT, SEQ/DC_NT, BATCH);
    decomp_kernel<<<dgrid, 256>>>(x, alpha, dw7, dw25, dw49);

    // 2) LN1(S) -> Sn
    ln_kernel<<<TOKENS, 256>>>(pS, n1g, n1b, pBuf);

    // 3) Q,K,V projections (tf32 mma.sync)
    dim3 gqkv(D_MODEL/128, TOKENS/128);
    tc_gemm<0><<<gqkv, 256, TCG_SMEM>>>(pBuf, qw, qb, pQ, D_MODEL, D_MODEL, nullptr, nullptr, 0);
    tc_gemm<0><<<gqkv, 256, TCG_SMEM>>>(pBuf, kw, kb, pK, D_MODEL, D_MODEL, nullptr, nullptr, 0);
    tc_gemm<0><<<gqkv, 256, TCG_SMEM>>>(pBuf, vw, vb, pV, D_MODEL, D_MODEL, nullptr, nullptr, 0);

    // 4) attention
    dim3 agrid(BATCH*NHEAD, SEQ/64);
    attn_kernel<<<agrid, 64>>>();

    // 5) O projection + residual S -> g_xs
    tc_gemm<2><<<gqkv, 256, TCG_SMEM>>>(pY, ow, ob, pXs, D_MODEL, D_MODEL, pS, nullptr, 0);

    // 6) LN2 -> xf
    ln_kernel<<<TOKENS, 256>>>(pXs, n2g, n2b, pBuf);

    // 7) router + aux
    router_kernel<<<TOKENS/8, 256>>>(pBuf, rw);
    aux_kernel<<<1, 256>>>(out, out_size);

    // 8) MoE FFN (dense 4 experts)
    dim3 gh1(MOE_HIDDEN/128, TOKENS/128);
    dim3 gh2(D_MODEL/128,    TOKENS/128);
    for (int e = 0; e < NUM_EXPERTS; e++) {
        tc_gemm<1><<<gh1, 256, TCG_SMEM>>>(pBuf, ew1 + (size_t)e*MOE_HIDDEN*D_MODEL,
                                           eb1 + (size_t)e*MOE_HIDDEN, pH,
                                           D_MODEL, MOE_HIDDEN, nullptr, nullptr, 0);
        tc_gemm<3><<<gh2, 256, TCG_SMEM>>>(pH, ew2 + (size_t)e*D_MODEL*MOE_HIDDEN,
                                           eb2 + (size_t)e*D_MODEL, pXs,
                                           MOE_HIDDEN, D_MODEL, nullptr, pW, e);
    }

    // 9) final
    final_kernel<<<(BND + 255)/256, 256>>>(tw, tb, out);
}

// round 5
// speedup vs baseline: 2.9472x; 1.2675x over previous
#include <cuda_runtime.h>
#include <math.h>
#include <stdint.h>

#define D_MODEL 1024
#define NHEAD 16
#define HEAD_DIM 64
#define MOE_HIDDEN 2048
#define NUM_EXPERTS 4
#define BATCH 8
#define SEQ 1024
#define TOKENS (BATCH*SEQ)          /* 8192  */
#define BND (TOKENS*D_MODEL)        /* 8388608 */
#define LN_EPS 1e-5f

// ---------------- scratch (device globals; no allocation) ----------------
__device__ float g_Tr[BND];
__device__ float g_S[BND];
__device__ float g_buf[BND];
__device__ float g_q[BND];
__device__ float g_k[BND];
__device__ float g_v[BND];
__device__ float g_y[BND];
__device__ float g_xs[BND];
__device__ float g_h[TOKENS*MOE_HIDDEN];
__device__ float g_w[TOKENS*NUM_EXPERTS];
__device__ float g_gates[TOKENS*NUM_EXPERTS];
__device__ int   g_elist[NUM_EXPERTS*TOKENS];   // per-expert token lists (padded)
__device__ int   g_ecnt[NUM_EXPERTS];

// ============================================================
// tf32 helpers (sm_80+ PTX, no 'a'-suffix gating)
// ============================================================
__device__ __forceinline__ uint32_t f2tf32(float f) {
    uint32_t u; asm("cvt.rna.tf32.f32 %0, %1;" : "=r"(u) : "f"(f)); return u;
}
__device__ __forceinline__ void mma_tf32(float* c, const uint32_t* a, const uint32_t* b) {
    asm volatile(
        "mma.sync.aligned.m16n8k8.row.col.f32.tf32.tf32.f32 "
        "{%0,%1,%2,%3}, {%4,%5,%6,%7}, {%8,%9}, {%0,%1,%2,%3};"
        : "+f"(c[0]), "+f"(c[1]), "+f"(c[2]), "+f"(c[3])
        : "r"(a[0]), "r"(a[1]), "r"(a[2]), "r"(a[3]), "r"(b[0]), "r"(b[1]));
}

// ============================================================
// tf32 mma.sync GEMM: C[m,n] = sum_k A[m,k]*B[n,k] (+bias, epilogue)
// CTA tile 128x128, BK=16, 256 thr (8 warps 2x4, warp tile 64x32),
// double-buffered smem [128][20], register-prefetch, 1 sync/K-iter,
// 2 CTAs/SM (regs capped at 128, smem 40KB).
// Optional row gather (aidx) for A, row scatter+guard (cidx,cnt) for C.
// EPI: 0 plain, 1 GELU, 2 +resid, 3 scatter C[row] += v*w[row,e]
// ============================================================
#define TCG_LDA 20
#define TCG_BUF (128*TCG_LDA)
#define TCG_SMEM (4*TCG_BUF*4)   /* 40960 B */

template<int EPI>
__global__ void __launch_bounds__(256, 2) tc_gemm(
    const float* __restrict__ A, const float* __restrict__ B,
    const float* __restrict__ bias, float* __restrict__ C,
    int K, int Nn,
    const float* __restrict__ resid, const float* __restrict__ wts, int expert,
    const int* __restrict__ aidx, const int* __restrict__ cidx,
    const int* __restrict__ cntp)
{
    extern __shared__ uint32_t smu[];
    const int tid = threadIdx.x;
    const int bm = blockIdx.y * 128, bn = blockIdx.x * 128;
    int cnt = 0x7fffffff;
    if (cntp) { cnt = *cntp; if (bm >= ((cnt + 127) & ~127)) return; }

    uint32_t* As = smu;                 // [2][128*20]
    uint32_t* Bs = smu + 2*TCG_BUF;
    const int warp = tid >> 5, lane = tid & 31;
    const int wm = (warp >> 2) * 64, wn = (warp & 3) * 32;
    const int g = lane >> 2, t = lane & 3;

    const int lr = tid >> 2, lc = tid & 3;   // staging: row(0..63), float4-col(0..3)
    int ra0 = bm + lr, ra1 = bm + lr + 64;
    if (aidx) { ra0 = aidx[ra0]; ra1 = aidx[ra1]; }
    const float* Ag0 = A + (size_t)ra0 * K + lc * 4;
    const float* Ag1 = A + (size_t)ra1 * K + lc * 4;
    const float* Bg0 = B + (size_t)(bn + lr) * K + lc * 4;
    const float* Bg1 = B + (size_t)(bn + lr + 64) * K + lc * 4;

    float acc[4][4][4];
    #pragma unroll
    for (int i = 0; i < 4; i++)
        #pragma unroll
        for (int j = 0; j < 4; j++)
            #pragma unroll
            for (int r = 0; r < 4; r++) acc[i][j][r] = 0.f;

    const int NT = K >> 4;
    float4 pa0 = *(const float4*)Ag0, pa1 = *(const float4*)Ag1;
    float4 pb0 = *(const float4*)Bg0, pb1 = *(const float4*)Bg1;
    {
        uint4 u0 = { f2tf32(pa0.x), f2tf32(pa0.y), f2tf32(pa0.z), f2tf32(pa0.w) };
        uint4 u1 = { f2tf32(pa1.x), f2tf32(pa1.y), f2tf32(pa1.z), f2tf32(pa1.w) };
        uint4 w0 = { f2tf32(pb0.x), f2tf32(pb0.y), f2tf32(pb0.z), f2tf32(pb0.w) };
        uint4 w1 = { f2tf32(pb1.x), f2tf32(pb1.y), f2tf32(pb1.z), f2tf32(pb1.w) };
        *(uint4*)&As[lr*TCG_LDA + lc*4]        = u0;
        *(uint4*)&As[(lr+64)*TCG_LDA + lc*4]   = u1;
        *(uint4*)&Bs[lr*TCG_LDA + lc*4]        = w0;
        *(uint4*)&Bs[(lr+64)*TCG_LDA + lc*4]   = w1;
    }
    __syncthreads();

    for (int kt = 0; kt < NT; kt++) {
        const uint32_t* Ab = As + (kt & 1)*TCG_BUF;
        const uint32_t* Bb = Bs + (kt & 1)*TCG_BUF;
        if (kt + 1 < NT) {
            const int ko = (kt + 1) * 16;
            pa0 = *(const float4*)(Ag0 + ko); pa1 = *(const float4*)(Ag1 + ko);
            pb0 = *(const float4*)(Bg0 + ko); pb1 = *(const float4*)(Bg1 + ko);
        }
        #pragma unroll
        for (int ks = 0; ks < 2; ks++) {
            const int kb = ks * 8;
            uint32_t af[4][4], bf[4][2];
            #pragma unroll
            for (int mf = 0; mf < 4; mf++) {
                const uint32_t* base = Ab + (wm + mf*16 + g)*TCG_LDA + kb + t;
                af[mf][0] = base[0];
                af[mf][1] = base[8*TCG_LDA];
                af[mf][2] = base[4];
                af[mf][3] = base[8*TCG_LDA + 4];
            }
            #pragma unroll
            for (int nf = 0; nf < 4; nf++) {
                const uint32_t* base = Bb + (wn + nf*8 + g)*TCG_LDA + kb + t;
                bf[nf][0] = base[0];
                bf[nf][1] = base[4];
            }
            #pragma unroll
            for (int mf = 0; mf < 4; mf++)
                #pragma unroll
                for (int nf = 0; nf < 4; nf++)
                    mma_tf32(acc[mf][nf], af[mf], bf[nf]);
        }
        if (kt + 1 < NT) {
            uint32_t* Ad = As + ((kt+1) & 1)*TCG_BUF;
            uint32_t* Bd = Bs + ((kt+1) & 1)*TCG_BUF;
            uint4 u0 = { f2tf32(pa0.x), f2tf32(pa0.y), f2tf32(pa0.z), f2tf32(pa0.w) };
            uint4 u1 = { f2tf32(pa1.x), f2tf32(pa1.y), f2tf32(pa1.z), f2tf32(pa1.w) };
            uint4 w0 = { f2tf32(pb0.x), f2tf32(pb0.y), f2tf32(pb0.z), f2tf32(pb0.w) };
            uint4 w1 = { f2tf32(pb1.x), f2tf32(pb1.y), f2tf32(pb1.z), f2tf32(pb1.w) };
            *(uint4*)&Ad[lr*TCG_LDA + lc*4]      = u0;
            *(uint4*)&Ad[(lr+64)*TCG_LDA + lc*4] = u1;
            *(uint4*)&Bd[lr*TCG_LDA + lc*4]      = w0;
            *(uint4*)&Bd[(lr+64)*TCG_LDA + lc*4] = w1;
            __syncthreads();
        }
    }

    // ---- epilogue ----
    #pragma unroll
    for (int mf = 0; mf < 4; mf++) {
        const int mp0 = bm + wm + mf*16 + g;
        const int mp1 = mp0 + 8;
        if (EPI == 3) {
            const int r0 = cidx[mp0], r1 = cidx[mp1];
            const float w0 = wts[r0*NUM_EXPERTS + expert];
            const float w1 = wts[r1*NUM_EXPERTS + expert];
            const bool ok0 = mp0 < cnt, ok1 = mp1 < cnt;
            #pragma unroll
            for (int nf = 0; nf < 4; nf++) {
                const int n0 = bn + wn + nf*8 + 2*t;
                const float b0 = bias[n0], b1 = bias[n0 + 1];
                const float v0 = acc[mf][nf][0] + b0;
                const float v1 = acc[mf][nf][1] + b1;
                const float v2 = acc[mf][nf][2] + b0;
                const float v3 = acc[mf][nf][3] + b1;
                if (ok0) {
                    const size_t i0 = (size_t)r0 * Nn + n0;
                    C[i0]   += v0 * w0;
                    C[i0+1] += v1 * w0;
                }
                if (ok1) {
                    const size_t i1 = (size_t)r1 * Nn + n0;
                    C[i1]   += v2 * w1;
                    C[i1+1] += v3 * w1;
                }
            }
        } else {
            #pragma unroll
            for (int nf = 0; nf < 4; nf++) {
                const int n0 = bn + wn + nf*8 + 2*t;
                const float b0 = bias[n0], b1 = bias[n0 + 1];
                float v0 = acc[mf][nf][0] + b0;
                float v1 = acc[mf][nf][1] + b1;
                float v2 = acc[mf][nf][2] + b0;
                float v3 = acc[mf][nf][3] + b1;
                const size_t i0 = (size_t)mp0 * Nn + n0;
                const size_t i1 = (size_t)mp1 * Nn + n0;
                if (EPI == 0) {
                    C[i0] = v0; C[i0+1] = v1; C[i1] = v2; C[i1+1] = v3;
                } else if (EPI == 1) {
                    C[i0]   = 0.5f*v0*(1.0f + erff(v0*0.70710678118654752f));
                    C[i0+1] = 0.5f*v1*(1.0f + erff(v1*0.70710678118654752f));
                    C[i1]   = 0.5f*v2*(1.0f + erff(v2*0.70710678118654752f));
                    C[i1+1] = 0.5f*v3*(1.0f + erff(v3*0.70710678118654752f));
                } else {
                    C[i0] = v0 + resid[i0]; C[i0+1] = v1 + resid[i0+1];
                    C[i1] = v2 + resid[i1]; C[i1+1] = v3 + resid[i1+1];
                }
            }
        }
    }
}

// ---------------- Decomp1D ----------------
#define DC_NT 128
#define DC_DT 32
#define DC_HALO 24
__global__ void __launch_bounds__(256) decomp_kernel(
    const float* __restrict__ x, const float* __restrict__ alpha,
    const float* __restrict__ dw7, const float* __restrict__ dw25,
    const float* __restrict__ dw49)
{
    __shared__ float sx[DC_NT + 2*DC_HALO][DC_DT];
    __shared__ float sw7[DC_DT][7];
    __shared__ float sw25[DC_DT][25];
    __shared__ float sw49[DC_DT][49];
    const int b  = blockIdx.z;
    const int n0 = blockIdx.y * DC_NT;
    const int d0 = blockIdx.x * DC_DT;
    const int tid = threadIdx.x;

    for (int i = tid; i < DC_DT*7;  i += 256) sw7 [i/7 ][i%7 ] = dw7 [(d0 + i/7 )*7  + i%7 ];
    for (int i = tid; i < DC_DT*25; i += 256) sw25[i/25][i%25] = dw25[(d0 + i/25)*25 + i%25];
    for (int i = tid; i < DC_DT*49; i += 256) sw49[i/49][i%49] = dw49[(d0 + i/49)*49 + i%49];

    for (int i = tid; i < (DC_NT + 2*DC_HALO)*DC_DT; i += 256) {
        int r = i / DC_DT, c = i % DC_DT;
        int n = n0 + r - DC_HALO;
        if (n < 0)    n = -n;
        if (n >= SEQ) n = 2*SEQ - 2 - n;
        sx[r][c] = x[((size_t)b*SEQ + n)*D_MODEL + d0 + c];
    }
    __syncthreads();

    const float a0 = alpha[0], a1 = alpha[1], a2 = alpha[2];
    const float mx = fmaxf(a0, fmaxf(a1, a2));
    const float e0 = __expf(a0-mx), e1 = __expf(a1-mx), e2 = __expf(a2-mx);
    const float inv = 1.f/(e0+e1+e2);
    const float w0 = e0*inv, w1 = e1*inv, w2 = e2*inv;

    for (int i = tid; i < DC_NT*DC_DT; i += 256) {
        const int p = i / DC_DT, c = i % DC_DT;
        float t7 = 0.f, t25 = 0.f, t49 = 0.f;
        #pragma unroll
        for (int j = 0; j < 7;  j++) t7  = fmaf(sx[p + DC_HALO - 3  + j][c], sw7 [c][j], t7 );
        #pragma unroll
        for (int j = 0; j < 25; j++) t25 = fmaf(sx[p + DC_HALO - 12 + j][c], sw25[c][j], t25);
        #pragma unroll
        for (int j = 0; j < 49; j++) t49 = fmaf(sx[p + j][c],                sw49[c][j], t49);
        const float tr = w0*t7 + w1*t25 + w2*t49;
        const size_t idx = ((size_t)b*SEQ + n0 + p)*D_MODEL + d0 + c;
        g_Tr[idx] = tr;
        g_S[idx]  = sx[p + DC_HALO][c] - tr;
    }
}

// ---------------- LayerNorm ----------------
__global__ void __launch_bounds__(256) ln_kernel(
    const float* __restrict__ in, const float* __restrict__ gam,
    const float* __restrict__ bet, float* __restrict__ out)
{
    __shared__ float row[D_MODEL];
    __shared__ float red[256];
    const int t = blockIdx.x, tid = threadIdx.x;
    const float* ip = in + (size_t)t*D_MODEL;
    float s = 0.f;
    for (int d = tid; d < D_MODEL; d += 256) { float v = ip[d]; row[d] = v; s += v; }
    red[tid] = s; __syncthreads();
    for (int o = 128; o > 0; o >>= 1) { if (tid < o) red[tid] += red[tid+o]; __syncthreads(); }
    const float mean = red[0] * (1.f/D_MODEL);
    __syncthreads();
    float vs = 0.f;
    for (int d = tid; d < D_MODEL; d += 256) { float dv = row[d]-mean; vs += dv*dv; }
    red[tid] = vs; __syncthreads();
    for (int o = 128; o > 0; o >>= 1) { if (tid < o) red[tid] += red[tid+o]; __syncthreads(); }
    const float rstd = rsqrtf(red[0] * (1.f/D_MODEL) + LN_EPS);
    for (int d = tid; d < D_MODEL; d += 256)
        out[(size_t)t*D_MODEL + d] = (row[d]-mean)*rstd*gam[d] + bet[d];
}

// ---------------- ALiBi attention ----------------
__global__ void __launch_bounds__(64) attn_kernel()
{
    __shared__ float Ks[64][64];
    __shared__ float Vs[64][64];
    const int bh = blockIdx.x;
    const int b = bh / NHEAD, h = bh % NHEAD;
    const int q0 = blockIdx.y * 64;
    const int tid = threadIdx.x;
    const int qg = q0 + tid;

    float q[64], o[64];
    const float* qp = g_q + ((size_t)(b*SEQ + qg))*D_MODEL + h*HEAD_DIM;
    #pragma unroll
    for (int d = 0; d < 64; d++) { q[d] = qp[d]*0.125f; o[d] = 0.f; }
    float l = 0.f;
    const float slope = exp2f(-0.5f*(float)(h+1));

    for (int k0 = 0; k0 < SEQ; k0 += 64) {
        const float* kp = g_k + ((size_t)(b*SEQ + k0))*D_MODEL + h*HEAD_DIM;
        const float* vp = g_v + ((size_t)(b*SEQ + k0))*D_MODEL + h*HEAD_DIM;
        __syncthreads();
        for (int r = 0; r < 64; r++) {
            Ks[r][tid] = kp[(size_t)r*D_MODEL + tid];
            Vs[r][tid] = vp[(size_t)r*D_MODEL + tid];
        }
        __syncthreads();
        #pragma unroll 4
        for (int j = 0; j < 64; j++) {
            float s = 0.f;
            #pragma unroll
            for (int d = 0; d < 64; d++) s = fmaf(q[d], Ks[j][d], s);
            const int dist = k0 + j - qg;
            if (dist > 0) s -= slope * (float)dist;
            const float p = __expf(s);
            l += p;
            #pragma unroll
            for (int d = 0; d < 64; d++) o[d] = fmaf(p, Vs[j][d], o[d]);
        }
    }
    const float invl = 1.f/l;
    float* yp = g_y + ((size_t)(b*SEQ + qg))*D_MODEL + h*HEAD_DIM;
    #pragma unroll
    for (int d = 0; d < 64; d++) yp[d] = o[d]*invl;
}

// ---------------- Router ----------------
__global__ void __launch_bounds__(256) router_kernel(
    const float* __restrict__ xf, const float* __restrict__ rw)
{
    const int warp = threadIdx.x / 32, lane = threadIdx.x % 32;
    const int t = blockIdx.x*8 + warp;
    const float* xp = xf + (size_t)t*D_MODEL;
    float logit[NUM_EXPERTS];
    #pragma unroll
    for (int e = 0; e < NUM_EXPERTS; e++) {
        float p = 0.f;
        for (int d = lane; d < D_MODEL; d += 32) p = fmaf(xp[d], rw[e*D_MODEL + d], p);
        #pragma unroll
        for (int o = 16; o > 0; o >>= 1) p += __shfl_xor_sync(0xffffffffu, p, o);
        logit[e] = p;
    }
    if (lane == 0) {
        float mx = logit[0];
        #pragma unroll
        for (int e = 1; e < NUM_EXPERTS; e++) mx = fmaxf(mx, logit[e]);
        float g[NUM_EXPERTS]; float s = 0.f;
        #pragma unroll
        for (int e = 0; e < NUM_EXPERTS; e++) { g[e] = expf(logit[e]-mx); s += g[e]; }
        #pragma unroll
        for (int e = 0; e < NUM_EXPERTS; e++) g[e] /= s;
        int i0 = 0;
        #pragma unroll
        for (int e = 1; e < NUM_EXPERTS; e++) if (g[e] > g[i0]) i0 = e;
        int i1 = -1;
        #pragma unroll
        for (int e = 0; e < NUM_EXPERTS; e++)
            if (e != i0 && (i1 < 0 || g[e] > g[i1])) i1 = e;
        const float s2 = fmaxf(g[i0] + g[i1], 1e-9f);
        float w[NUM_EXPERTS] = {0.f, 0.f, 0.f, 0.f};
        w[i0] = g[i0]/s2; w[i1] = g[i1]/s2;
        #pragma unroll
        for (int e = 0; e < NUM_EXPERTS; e++) {
            g_gates[t*NUM_EXPERTS + e] = g[e];
            g_w[t*NUM_EXPERTS + e]     = w[e];
        }
    }
}

// ---------------- routing lists (deterministic stable partition) ----------------
__global__ void __launch_bounds__(128) route_kernel()
{
    const int e = threadIdx.x >> 5, lane = threadIdx.x & 31;
    int cnt = 0;
    for (int base = 0; base < TOKENS; base += 32) {
        const int t = base + lane;
        const bool sel = g_w[t*NUM_EXPERTS + e] > 0.f;
        const unsigned m = __ballot_sync(0xffffffffu, sel);
        if (sel) g_elist[e*TOKENS + cnt + __popc(m & ((1u << lane) - 1u))] = t;
        cnt += __popc(m);
    }
    __syncwarp();
    const int padded = (cnt + 127) & ~127;
    if (cnt > 0) {
        const int last = g_elist[e*TOKENS + cnt - 1];
        for (int i = cnt + lane; i < padded; i += 32) g_elist[e*TOKENS + i] = last;
    }
    if (lane == 0) g_ecnt[e] = cnt;
}

// ---------------- aux ----------------
__global__ void __launch_bounds__(256) aux_kernel(float* __restrict__ out, int out_size)
{
    __shared__ float rg[NUM_EXPERTS][256];
    __shared__ float rc[NUM_EXPERTS][256];
    const int tid = threadIdx.x;
    float gs[NUM_EXPERTS] = {0,0,0,0}, cs[NUM_EXPERTS] = {0,0,0,0};
    for (int t = tid; t < TOKENS; t += 256) {
        #pragma unroll
        for (int e = 0; e < NUM_EXPERTS; e++) {
            gs[e] += g_gates[t*NUM_EXPERTS + e];
            cs[e] += (g_w[t*NUM_EXPERTS + e] > 0.f) ? 1.f : 0.f;
        }
    }
    #pragma unroll
    for (int e = 0; e < NUM_EXPERTS; e++) { rg[e][tid] = gs[e]; rc[e][tid] = cs[e]; }
    __syncthreads();
    for (int o = 128; o > 0; o >>= 1) {
        if (tid < o)
            #pragma unroll
            for (int e = 0; e < NUM_EXPERTS; e++) { rg[e][tid] += rg[e][tid+o]; rc[e][tid] += rc[e][tid+o]; }
        __syncthreads();
    }
    if (tid == 0 && out_size > BND) {
        float aux = 0.f;
        #pragma unroll
        for (int e = 0; e < NUM_EXPERTS; e++)
            aux += (rg[e][0]*(1.f/TOKENS)) * (rc[e][0]*(1.f/TOKENS));
        out[out_size - 1] = (float)NUM_EXPERTS * aux;
    }
}

// ---------------- final ----------------
__global__ void __launch_bounds__(256) final_kernel(
    const float* __restrict__ tw, const float* __restrict__ tb, float* __restrict__ out)
{
    const size_t gid = (size_t)blockIdx.x*256 + threadIdx.x;
    if (gid >= (size_t)BND) return;
    const int d = (int)(gid % D_MODEL);
    const int n = (int)((gid / D_MODEL) % SEQ);
    float t = 0.f;
    #pragma unroll
    for (int j = 0; j < 5; j++) {
        const int nn = n - 2 + j;
        if (nn >= 0 && nn < SEQ)
            t = fmaf(g_Tr[gid + (size_t)(j-2)*D_MODEL], tw[d*5 + j], t);
    }
    out[gid] = g_xs[gid] + t + tb[d];
}

// ---------------- launch ----------------
static float* sym_addr(const void* sym) {
    void* p = nullptr;
    cudaGetSymbolAddress(&p, sym);
    return (float*)p;
}

extern "C" void kernel_launch(void* const* d_in, const int* in_sizes, int n_in,
                              void* d_out, int out_size)
{
    const float* x    = (const float*)d_in[0];
    const float* qw   = (const float*)d_in[1];  const float* qb  = (const float*)d_in[2];
    const float* kw   = (const float*)d_in[3];  const float* kb  = (const float*)d_in[4];
    const float* vw   = (const float*)d_in[5];  const float* vb  = (const float*)d_in[6];
    const float* ow   = (const float*)d_in[7];  const float* ob  = (const float*)d_in[8];
    const float* n1g  = (const float*)d_in[9];  const float* n1b = (const float*)d_in[10];
    const float* n2g  = (const float*)d_in[11]; const float* n2b = (const float*)d_in[12];
    const float* alpha= (const float*)d_in[13];
    const float* dw7  = (const float*)d_in[14];
    const float* dw25 = (const float*)d_in[15];
    const float* dw49 = (const float*)d_in[16];
    const float* rw   = (const float*)d_in[17];
    const float* ew1  = (const float*)d_in[18]; const float* eb1 = (const float*)d_in[19];
    const float* ew2  = (const float*)d_in[20]; const float* eb2 = (const float*)d_in[21];
    const float* tw   = (const float*)d_in[22]; const float* tb  = (const float*)d_in[23];
    float* out = (float*)d_out;

    float* pS   = sym_addr(g_S);
    float* pBuf = sym_addr(g_buf);
    float* pQ   = sym_addr(g_q);
    float* pK   = sym_addr(g_k);
    float* pV   = sym_addr(g_v);
    float* pY   = sym_addr(g_y);
    float* pXs  = sym_addr(g_xs);
    float* pH   = sym_addr(g_h);
    float* pW   = sym_addr(g_w);
    int*   pEL  = (int*)sym_addr(g_elist);
    int*   pEC  = (int*)sym_addr(g_ecnt);
    (void)in_sizes; (void)n_in;

    // 1) decomposition -> g_Tr, g_S
    dim3 dgrid(D_MODEL/DC_DT, SEQ/DC_NT, BATCH);
    decomp_kernel<<<dgrid, 256>>>(x, alpha, dw7, dw25, dw49);

    // 2) LN1(S) -> Sn
    ln_kernel<<<TOKENS, 256>>>(pS, n1g, n1b, pBuf);

    // 3) Q,K,V projections (tf32 mma.sync)
    dim3 gqkv(D_MODEL/128, TOKENS/128);
    tc_gemm<0><<<gqkv, 256, TCG_SMEM>>>(pBuf, qw, qb, pQ, D_MODEL, D_MODEL,
                                        nullptr, nullptr, 0, nullptr, nullptr, nullptr);
    tc_gemm<0><<<gqkv, 256, TCG_SMEM>>>(pBuf, kw, kb, pK, D_MODEL, D_MODEL,
                                        nullptr, nullptr, 0, nullptr, nullptr, nullptr);
    tc_gemm<0><<<gqkv, 256, TCG_SMEM>>>(pBuf, vw, vb, pV, D_MODEL, D_MODEL,
                                        nullptr, nullptr, 0, nullptr, nullptr, nullptr);

    // 4) attention
    dim3 agrid(BATCH*NHEAD, SEQ/64);
    attn_kernel<<<agrid, 64>>>();

    // 5) O projection + residual S -> g_xs
    tc_gemm<2><<<gqkv, 256, TCG_SMEM>>>(pY, ow, ob, pXs, D_MODEL, D_MODEL,
                                        pS, nullptr, 0, nullptr, nullptr, nullptr);

    // 6) LN2 -> xf
    ln_kernel<<<TOKENS, 256>>>(pXs, n2g, n2b, pBuf);

    // 7) router + routing lists + aux
    router_kernel<<<TOKENS/8, 256>>>(pBuf, rw);
    route_kernel<<<1, 128>>>();
    aux_kernel<<<1, 256>>>(out, out_size);

    // 8) MoE FFN: routed top-2 (exact-equivalent to dense)
    dim3 gh1(MOE_HIDDEN/128, TOKENS/128);
    dim3 gh2(D_MODEL/128,    TOKENS/128);
    for (int e = 0; e < NUM_EXPERTS; e++) {
        tc_gemm<1><<<gh1, 256, TCG_SMEM>>>(pBuf, ew1 + (size_t)e*MOE_HIDDEN*D_MODEL,
                                           eb1 + (size_t)e*MOE_HIDDEN, pH,
                                           D_MODEL, MOE_HIDDEN,
                                           nullptr, nullptr, 0,
                                           pEL + e*TOKENS, nullptr, pEC + e);
        tc_gemm<3><<<gh2, 256, TCG_SMEM>>>(pH, ew2 + (size_t)e*D_MODEL*MOE_HIDDEN,
                                           eb2 + (size_t)e*D_MODEL, pXs,
                                           MOE_HIDDEN, D_MODEL,
                                           nullptr, pW, e,
                                           nullptr, pEL + e*TOKENS, pEC + e);
    }

    // 9) final
    final_kernel<<<(BND + 255)/256, 256>>>(tw, tb, out);
}